// round 17
// baseline (speedup 1.0000x reference)
#include <cuda_runtime.h>
#include <cuda_bf16.h>
#include <cuda_fp16.h>
#include <math.h>
#include <stdint.h>

#define IN_F   256
#define OUT_F  256
#define N_E    10000
#define N_KC   2000
#define ALPHA  0.2f

#define MT      64
#define KC      32
#define NKC_PAD 2048
#define NCHUNK_RUN 63
#define RSTRIDE 80

#define NGEX    158
#define NATTN   157
#define NATTN2  (2 * NATTN)

typedef __nv_bfloat16 bf16;

// ---------------- scratch ----------------
__device__ __half g_exEhh[N_E * OUT_F];
__device__ float g_v1[IN_F];
__device__ float g_v2[IN_F];
__device__ __half g_kcWhT[OUT_F * NKC_PAD];
__device__ float g_colmean[OUT_F];
__device__ float g_mkcp[8][IN_F];
__device__ float g_Ae[N_E];
__device__ float g_Ce[N_E];
__device__ float2 g_tab[NKC_PAD];
__device__ __half g_exh[N_E * IN_F];
__device__ __half g_ETh[OUT_F * IN_F];
__device__ bf16 g_kchi[N_KC * IN_F];
__device__ bf16 g_kclo[N_KC * IN_F];
__device__ bf16 g_W1Thi[OUT_F * IN_F];
__device__ bf16 g_W1Tlo[OUT_F * IN_F];
__device__ __half g_rdwh[OUT_F * 2 * OUT_F];
__device__ __half g_feath[N_E * OUT_F];
// split-K partials
__device__ float g_pacc[2][N_E * OUT_F];
__device__ float g_psr[2][NATTN * MT];
__device__ int   g_cnt[NATTN];

// ---------------- helpers ----------------
static __device__ __forceinline__ uint32_t smem_u32(const void* p) {
    uint32_t a;
    asm("{ .reg .u64 t; cvta.to.shared.u64 t, %1; cvt.u32.u64 %0, t; }" : "=r"(a) : "l"(p));
    return a;
}
#define LDSM_X4(R0,R1,R2,R3,ADDR) \
    asm volatile("ldmatrix.sync.aligned.m8n8.x4.shared.b16 {%0,%1,%2,%3}, [%4];" \
                 : "=r"(R0),"=r"(R1),"=r"(R2),"=r"(R3) : "r"(ADDR))
#define CP_ASYNC16(dst, src) \
    asm volatile("cp.async.ca.shared.global [%0], [%1], 16;" :: "r"(dst), "l"(src))
#define CP_COMMIT() asm volatile("cp.async.commit_group;" ::: "memory")
#define CP_WAIT0()  asm volatile("cp.async.wait_group 0;" ::: "memory")

static __device__ __forceinline__ void mma_bf16(float* c, const uint32_t* a, const uint32_t* b) {
    asm volatile(
        "mma.sync.aligned.m16n8k16.row.col.f32.bf16.bf16.f32 "
        "{%0,%1,%2,%3}, {%4,%5,%6,%7}, {%8,%9}, {%0,%1,%2,%3};"
        : "+f"(c[0]), "+f"(c[1]), "+f"(c[2]), "+f"(c[3])
        : "r"(a[0]), "r"(a[1]), "r"(a[2]), "r"(a[3]), "r"(b[0]), "r"(b[1]));
}
static __device__ __forceinline__ void mma_fp16(float* c, const uint32_t* a, const uint32_t* b) {
    asm volatile(
        "mma.sync.aligned.m16n8k16.row.col.f32.f16.f16.f32 "
        "{%0,%1,%2,%3}, {%4,%5,%6,%7}, {%8,%9}, {%0,%1,%2,%3};"
        : "+f"(c[0]), "+f"(c[1]), "+f"(c[2]), "+f"(c[3])
        : "r"(a[0]), "r"(a[1]), "r"(a[2]), "r"(a[3]), "r"(b[0]), "r"(b[1]));
}
static __device__ __forceinline__ void fsplit(float v, bf16& h, bf16& l) {
    h = __float2bfloat16(v);
    l = __float2bfloat16(v - __bfloat162float(h));
}
static __device__ __forceinline__ uint32_t pack2(bf16 a, bf16 b) {
    __nv_bfloat162 t = __halves2bfloat162(a, b);
    return *(uint32_t*)&t;
}
static __device__ __forceinline__ void split4_store(const float4 v, bf16* hi, bf16* lo) {
    bf16 h0, l0, h1, l1, h2, l2, h3, l3;
    fsplit(v.x, h0, l0); fsplit(v.y, h1, l1);
    fsplit(v.z, h2, l2); fsplit(v.w, h3, l3);
    *(uint32_t*)(hi)     = pack2(h0, h1);
    *(uint32_t*)(hi + 2) = pack2(h2, h3);
    *(uint32_t*)(lo)     = pack2(l0, l1);
    *(uint32_t*)(lo + 2) = pack2(l2, l3);
}
static __device__ __forceinline__ void half4_store(const float4 v, __half* dst) {
    __half2 a0 = __floats2half2_rn(v.x, v.y);
    __half2 a1 = __floats2half2_rn(v.z, v.w);
    *(uint32_t*)(dst)     = *(uint32_t*)&a0;
    *(uint32_t*)(dst + 2) = *(uint32_t*)&a1;
}

// ---------------- k0: v1/v2 + flag reset + tab padding ----------------
__global__ void k0_kernel(const float* __restrict__ W1, const float* __restrict__ a)
{
    int k = threadIdx.x;
    float s1 = 0.f, s2 = 0.f;
    #pragma unroll 8
    for (int j = 0; j < OUT_F; j++) {
        float w = W1[k * OUT_F + j];
        s1 += w * a[j];
        s2 += w * a[OUT_F + j];
    }
    g_v1[k] = s1;
    g_v2[k] = s2;
    if (k < NATTN) g_cnt[k] = 0;
    if (k < NKC_PAD - N_KC) g_tab[N_KC + k] = make_float2(0.f, 0.f);
}

// ---------------- mega kernel: conversions + fused rowdots + colsum partials ----------------
#define MB_KC   2500
#define MB_RDW  3000
#define MB_TW1  3128
#define MB_TE   3192
#define MB_MKC  3256
#define MB_TOT  3264
__global__ void mega_kernel(const float* __restrict__ ex, const float* __restrict__ kc,
                            const float* __restrict__ rdw, const float* __restrict__ W1,
                            const float* __restrict__ E)
{
    int b = blockIdx.x, tid = threadIdx.x;
    if (b < MB_KC) {
        // ex -> fp16, fused e1 rowdot (4 rows per block)
        __shared__ float wp[8];
        size_t i = ((size_t)b * 256 + tid) * 4;
        float4 v = *(const float4*)(ex + i);
        half4_store(v, g_exh + i);
        int col = (tid * 4) & 255;
        float s = v.x * g_v1[col] + v.y * g_v1[col + 1]
                + v.z * g_v1[col + 2] + v.w * g_v1[col + 3];
        #pragma unroll
        for (int o = 16; o; o >>= 1) s += __shfl_xor_sync(0xFFFFFFFFu, s, o);
        if ((tid & 31) == 0) wp[tid >> 5] = s;
        __syncthreads();
        if (tid < 4) {
            float t = wp[2 * tid] + wp[2 * tid + 1];
            int row = b * 4 + tid;
            g_Ae[row] = __expf(t);
            g_Ce[row] = __expf(ALPHA * t);
        }
    } else if (b < MB_RDW) {
        // kc -> bf16 hi/lo, fused e2/tab rowdot (4 rows per block)
        __shared__ float wp[8];
        size_t i = ((size_t)(b - MB_KC) * 256 + tid) * 4;
        float4 v = *(const float4*)(kc + i);
        split4_store(v, g_kchi + i, g_kclo + i);
        int col = (tid * 4) & 255;
        float s = v.x * g_v2[col] + v.y * g_v2[col + 1]
                + v.z * g_v2[col + 2] + v.w * g_v2[col + 3];
        #pragma unroll
        for (int o = 16; o; o >>= 1) s += __shfl_xor_sync(0xFFFFFFFFu, s, o);
        if ((tid & 31) == 0) wp[tid >> 5] = s;
        __syncthreads();
        if (tid < 4) {
            float t = wp[2 * tid] + wp[2 * tid + 1];
            int j = (b - MB_KC) * 4 + tid;
            g_tab[j] = make_float2(__expf(t), __expf(ALPHA * t));
        }
    } else if (b < MB_TW1) {
        size_t i = ((size_t)(b - MB_RDW) * 256 + tid) * 4;
        half4_store(*(const float4*)(rdw + i), g_rdwh + i);
    } else if (b < MB_TE) {
        int bb = b - MB_TW1;
        __shared__ float t[32][33];
        int kb = (bb & 7) * 32, nb = (bb >> 3) * 32;
        int tx = tid & 31, ty = tid >> 5;
        #pragma unroll
        for (int rr = 0; rr < 32; rr += 8)
            t[ty + rr][tx] = W1[(size_t)(kb + ty + rr) * OUT_F + nb + tx];
        __syncthreads();
        #pragma unroll
        for (int rr = 0; rr < 32; rr += 8) {
            int n = nb + ty + rr;
            bf16 h, l;
            fsplit(t[tx][ty + rr], h, l);
            g_W1Thi[(size_t)n * IN_F + kb + tx] = h;
            g_W1Tlo[(size_t)n * IN_F + kb + tx] = l;
        }
    } else if (b < MB_MKC) {
        int bb = b - MB_TE;
        __shared__ float t[32][33];
        int kb = (bb & 7) * 32, nb = (bb >> 3) * 32;
        int tx = tid & 31, ty = tid >> 5;
        #pragma unroll
        for (int rr = 0; rr < 32; rr += 8)
            t[ty + rr][tx] = E[(size_t)(kb + ty + rr) * OUT_F + nb + tx];
        __syncthreads();
        #pragma unroll
        for (int rr = 0; rr < 32; rr += 8) {
            int n = nb + ty + rr;
            g_ETh[(size_t)n * IN_F + kb + tx] = __float2half_rn(t[tx][ty + rr]);
        }
    } else {
        int p = b - MB_MKC;
        float s = 0.f;
        for (int j = p * 250; j < (p + 1) * 250; j++)
            s += kc[(size_t)j * IN_F + tid];
        g_mkcp[p][tid] = s;
    }
}

// ---------------- hgemm body (128x128) ----------------
// use16==0: bf16 hi/lo 3-product. use16==1: fp16 single product.
// epi: 0 plain fp32; 2 -> g_kcWhT transposed fp16; 3 -> fp16 C write.
#define HOF_AH 0
#define HOF_AL 10240
#define HOF_BH 20480
#define HOF_BL 30720
static __device__ __forceinline__ void hgemm_body(char* smem,
    const bf16* __restrict__ Ahi, const bf16* __restrict__ Alo,
    const bf16* __restrict__ Bhi, const bf16* __restrict__ Blo,
    float* __restrict__ C, int M, int N, int K,
    int epi, int bx, int by, int use16)
{
    uint32_t sb = smem_u32(smem);
    int tid = threadIdx.x, lane = tid & 31, wid = tid >> 5;
    int bm = by * 128, bn = bx * 128;
    int wm = wid >> 1, wn = wid & 1;

    float acc[2][8][4];
    #pragma unroll
    for (int mt = 0; mt < 2; mt++)
        #pragma unroll
        for (int nb = 0; nb < 8; nb++)
            #pragma unroll
            for (int k = 0; k < 4; k++) acc[mt][nb][k] = 0.f;

    int crow = tid >> 1, chalf = tid & 1;
    bool arow_ok = (bm + crow) < M;
    const uint4 zero4 = make_uint4(0, 0, 0, 0);

    for (int k0 = 0; k0 < K; k0 += 32) {
        {
            char* dh = smem + HOF_AH + crow * RSTRIDE + chalf * 32;
            char* dl = smem + HOF_AL + crow * RSTRIDE + chalf * 32;
            if (!arow_ok) {
                ((uint4*)dh)[0] = zero4; ((uint4*)dh)[1] = zero4;
                if (!use16) { ((uint4*)dl)[0] = zero4; ((uint4*)dl)[1] = zero4; }
            } else {
                const uint4* sh = (const uint4*)(Ahi + (size_t)(bm + crow) * K + k0 + chalf * 16);
                ((uint4*)dh)[0] = sh[0]; ((uint4*)dh)[1] = sh[1];
                if (!use16) {
                    const uint4* sl = (const uint4*)(Alo + (size_t)(bm + crow) * K + k0 + chalf * 16);
                    ((uint4*)dl)[0] = sl[0]; ((uint4*)dl)[1] = sl[1];
                }
            }
        }
        {
            const uint4* sh = (const uint4*)(Bhi + (size_t)(bn + crow) * K + k0 + chalf * 16);
            char* dh = smem + HOF_BH + crow * RSTRIDE + chalf * 32;
            ((uint4*)dh)[0] = sh[0]; ((uint4*)dh)[1] = sh[1];
            if (!use16) {
                const uint4* sl = (const uint4*)(Blo + (size_t)(bn + crow) * K + k0 + chalf * 16);
                char* dl = smem + HOF_BL + crow * RSTRIDE + chalf * 32;
                ((uint4*)dl)[0] = sl[0]; ((uint4*)dl)[1] = sl[1];
            }
        }
        __syncthreads();

        #pragma unroll
        for (int ks = 0; ks < 2; ks++) {
            uint32_t ahi[2][4], alo[2][4], bfrag[8][2];
            int arowi = lane & 15;
            int akoff = (ks * 16 + ((lane >> 4) & 1) * 8) * 2;
            #pragma unroll
            for (int mt = 0; mt < 2; mt++) {
                uint32_t ad = sb + HOF_AH + (wm * 32 + mt * 16 + arowi) * RSTRIDE + akoff;
                LDSM_X4(ahi[mt][0], ahi[mt][1], ahi[mt][2], ahi[mt][3], ad);
                if (!use16) {
                    ad += (HOF_AL - HOF_AH);
                    LDSM_X4(alo[mt][0], alo[mt][1], alo[mt][2], alo[mt][3], ad);
                }
            }
            int bnrow = (lane & 7) + ((lane >> 4) << 3);
            int bkoff = (ks * 16 + ((lane >> 3) & 1) * 8) * 2;
            #pragma unroll
            for (int nq = 0; nq < 4; nq++) {
                uint32_t bd = sb + HOF_BH + (wn * 64 + nq * 16 + bnrow) * RSTRIDE + bkoff;
                LDSM_X4(bfrag[2 * nq][0], bfrag[2 * nq][1],
                        bfrag[2 * nq + 1][0], bfrag[2 * nq + 1][1], bd);
            }
            if (use16) {
                #pragma unroll
                for (int mt = 0; mt < 2; mt++)
                    #pragma unroll
                    for (int nb = 0; nb < 8; nb++)
                        mma_fp16(acc[mt][nb], ahi[mt], bfrag[nb]);
            } else {
                #pragma unroll
                for (int mt = 0; mt < 2; mt++)
                    #pragma unroll
                    for (int nb = 0; nb < 8; nb++)
                        mma_bf16(acc[mt][nb], ahi[mt], bfrag[nb]);
                #pragma unroll
                for (int mt = 0; mt < 2; mt++)
                    #pragma unroll
                    for (int nb = 0; nb < 8; nb++)
                        mma_bf16(acc[mt][nb], alo[mt], bfrag[nb]);
                #pragma unroll
                for (int nq = 0; nq < 4; nq++) {
                    uint32_t bd = sb + HOF_BL + (wn * 64 + nq * 16 + bnrow) * RSTRIDE + bkoff;
                    LDSM_X4(bfrag[2 * nq][0], bfrag[2 * nq][1],
                            bfrag[2 * nq + 1][0], bfrag[2 * nq + 1][1], bd);
                }
                #pragma unroll
                for (int mt = 0; mt < 2; mt++)
                    #pragma unroll
                    for (int nb = 0; nb < 8; nb++)
                        mma_bf16(acc[mt][nb], ahi[mt], bfrag[nb]);
            }
        }
        __syncthreads();
    }

    #pragma unroll
    for (int mt = 0; mt < 2; mt++) {
        #pragma unroll
        for (int nb = 0; nb < 8; nb++) {
            int row0 = wm * 32 + mt * 16 + (lane >> 2);
            int col = bn + wn * 64 + nb * 8 + (lane & 3) * 2;
            #pragma unroll
            for (int h = 0; h < 2; h++) {
                int r = bm + row0 + h * 8;
                float v0 = acc[mt][nb][2 * h];
                float v1 = acc[mt][nb][2 * h + 1];
                if (epi == 2) {
                    size_t base = ((size_t)(r >> 5) * 256);
                    g_kcWhT[(base + col)     * KC + (r & 31)] = __float2half_rn(v0);
                    g_kcWhT[(base + col + 1) * KC + (r & 31)] = __float2half_rn(v1);
                    continue;
                }
                if (r >= M) continue;
                if (epi == 3) {
                    __half2 t = __floats2half2_rn(v0, v1);
                    *(uint32_t*)((__half*)C + (size_t)r * N + col) = *(uint32_t*)&t;
                } else {
                    C[(size_t)r * N + col]     = v0;
                    C[(size_t)r * N + col + 1] = v1;
                }
            }
        }
    }
}

// ---------------- fgemm64: final GEMM, 64x64 tiles, fp16 single product ----------------
#define G64_A 0
#define G64_B 5120
#define G64_SMEM 10240
__global__ __launch_bounds__(256, 4) void fgemm64_kernel(const float* __restrict__ bias,
                                                         float* __restrict__ out)
{
    __shared__ char smem[G64_SMEM];
    uint32_t sb = smem_u32(smem);
    int tid = threadIdx.x, lane = tid & 31, wid = tid >> 5;
    int bm = blockIdx.y * 64, bn = blockIdx.x * 64;
    int wm = wid & 1, wn = wid >> 1;   // 2M x 4N, warp tile 32x16

    float acc[2][2][4];
    #pragma unroll
    for (int mt = 0; mt < 2; mt++)
        #pragma unroll
        for (int nb = 0; nb < 2; nb++)
            #pragma unroll
            for (int k = 0; k < 4; k++) acc[mt][nb][k] = 0.f;

    int crow = tid >> 2, cq = tid & 3;   // 4 threads/row x 16B (64B rows)
    bool arow_ok = (bm + crow) < N_E;
    const uint4 zero4 = make_uint4(0, 0, 0, 0);

    for (int k0 = 0; k0 < 2 * OUT_F; k0 += 32) {
        {
            char* d = smem + G64_A + crow * RSTRIDE + cq * 16;
            if (!arow_ok) {
                *(uint4*)d = zero4;
            } else if (k0 < 256) {
                *(uint4*)d = *(const uint4*)(g_feath + (size_t)(bm + crow) * 256 + k0 + cq * 8);
            } else {
                size_t rb = (size_t)(bm + crow) * 256 + (k0 - 256) + cq * 8;
                uint4 vh = *(const uint4*)(g_feath + rb);
                uint4 vx = *(const uint4*)(g_exEhh + rb);
                const __half2* ph = (const __half2*)&vh;
                const __half2* px = (const __half2*)&vx;
                uint32_t o[4];
                #pragma unroll
                for (int e = 0; e < 4; e++) {
                    __half2 t = __hmul2(ph[e], px[e]);
                    o[e] = *(uint32_t*)&t;
                }
                *(uint4*)d = *(uint4*)o;
            }
        }
        {
            const uint4* s4 = (const uint4*)(g_rdwh + (size_t)(bn + crow) * (2 * OUT_F) + k0 + cq * 8);
            char* d = smem + G64_B + crow * RSTRIDE + cq * 16;
            *(uint4*)d = *s4;
        }
        __syncthreads();

        #pragma unroll
        for (int ks = 0; ks < 2; ks++) {
            uint32_t af[2][4], bfrag[2][2];
            int arowi = lane & 15;
            int akoff = (ks * 16 + ((lane >> 4) & 1) * 8) * 2;
            #pragma unroll
            for (int mt = 0; mt < 2; mt++) {
                uint32_t ad = sb + G64_A + (wm * 32 + mt * 16 + arowi) * RSTRIDE + akoff;
                LDSM_X4(af[mt][0], af[mt][1], af[mt][2], af[mt][3], ad);
            }
            int bnrow = (lane & 7) + ((lane >> 4) << 3);
            int bkoff = (ks * 16 + ((lane >> 3) & 1) * 8) * 2;
            {
                uint32_t bd = sb + G64_B + (wn * 16 + bnrow) * RSTRIDE + bkoff;
                LDSM_X4(bfrag[0][0], bfrag[0][1], bfrag[1][0], bfrag[1][1], bd);
            }
            #pragma unroll
            for (int mt = 0; mt < 2; mt++)
                #pragma unroll
                for (int nb = 0; nb < 2; nb++)
                    mma_fp16(acc[mt][nb], af[mt], bfrag[nb]);
        }
        __syncthreads();
    }

    #pragma unroll
    for (int mt = 0; mt < 2; mt++) {
        #pragma unroll
        for (int nb = 0; nb < 2; nb++) {
            int row0 = wm * 32 + mt * 16 + (lane >> 2);
            int col = bn + wn * 16 + nb * 8 + (lane & 3) * 2;
            #pragma unroll
            for (int h = 0; h < 2; h++) {
                int r = bm + row0 + h * 8;
                if (r >= N_E) continue;
                float v0 = acc[mt][nb][2 * h] + bias[col];
                float v1 = acc[mt][nb][2 * h + 1] + bias[col + 1];
                v0 = v0 > 0.f ? v0 : expm1f(v0);
                v1 = v1 > 0.f ? v1 : expm1f(v1);
                out[(size_t)r * OUT_F + col]     = v0;
                out[(size_t)r * OUT_F + col + 1] = v1;
            }
        }
    }
}

// ---------------- prep2: kcWh gemm (-> g_kcWhT) + colmean ----------------
#define P2_GEMM 32
#define P2_TOT  33
__global__ __launch_bounds__(256, 2) void prep2_kernel(const float* __restrict__ W1)
{
    extern __shared__ char smem[];
    int b = blockIdx.x, tid = threadIdx.x;
    if (b < P2_GEMM) {
        hgemm_body(smem, g_kchi, g_kclo, g_W1Thi, g_W1Tlo, nullptr,
                   N_KC, OUT_F, IN_F, 2, b & 1, b >> 1, 0);
    } else {
        __shared__ float S[IN_F];
        float s = 0.f;
        #pragma unroll
        for (int p = 0; p < 8; p++) s += g_mkcp[p][tid];
        S[tid] = s;
        __syncthreads();
        float c = 0.f;
        #pragma unroll 8
        for (int k = 0; k < IN_F; k++)
            c += S[k] * W1[(size_t)k * OUT_F + tid];
        g_colmean[tid] = c * (1.0f / N_KC);
    }
}

// ---------------- attention body: single fp16 product, split-K, cp.async ----------------
#define AOF_B    0
#define AOF_BSZ  20480
#define AOF_A    40960
#define AOF_ASZ  5120
#define AOF_AE   51200
#define AOF_CE   51456
#define AOF_RS   51712
#define AOF_RSF  52736
#define SMEM_ATTN 53248

static __device__ __forceinline__ void cp_b_chunk(uint32_t sbB, int c, int tid)
{
    const __half* sh = g_kcWhT + ((size_t)c * 256 + tid) * KC;
    uint32_t dh = sbB + tid * RSTRIDE;
    #pragma unroll
    for (int t = 0; t < 4; t++)
        CP_ASYNC16(dh + t * 16, (const char*)sh + t * 16);
    CP_COMMIT();
}

static __device__ __forceinline__ void attn_body(char* smem, int tile, int half,
    const int* __restrict__ adj)
{
    uint32_t sb = smem_u32(smem);
    float* Aes = (float*)(smem + AOF_AE);
    float* Ces = (float*)(smem + AOF_CE);

    int tid = threadIdx.x, lane = tid & 31, wid = tid >> 5;
    int i0 = tile * MT;
    int c0 = half ? 32 : 0;
    int c1 = half ? NCHUNK_RUN : 32;

    cp_b_chunk(sb + AOF_B, c0, tid);

    if (tid < MT) {
        int gi = i0 + tid;
        bool v = gi < N_E;
        Aes[tid] = v ? g_Ae[gi] : 0.f;
        Ces[tid] = v ? g_Ce[gi] : 0.f;
    }
    __syncthreads();

    int r = tid >> 2, jl0 = (tid & 3) * 8;
    int gi_r = i0 + r;
    const int* arow = adj + (size_t)(gi_r < N_E ? gi_r : 0) * N_KC;
    float Ai = Aes[r], Ci = Ces[r];
    float srow = 0.f;

    int wm = wid & 1, wn = wid >> 1;
    float acc[2][8][4];
    #pragma unroll
    for (int mt = 0; mt < 2; mt++)
        #pragma unroll
        for (int nb = 0; nb < 8; nb++)
            #pragma unroll
            for (int k = 0; k < 4; k++) acc[mt][nb][k] = 0.f;

    for (int c = c0; c < c1; c++) {
        int buf = (c - c0) & 1;
        int j0 = c * KC;
        uint32_t aBase = sb + AOF_A + buf * AOF_ASZ;

        {
            float p[8];
            if (j0 + KC <= N_KC) {
                const int4* ap = (const int4*)(arow + j0 + jl0);
                int4 a0 = ap[0], a1 = ap[1];
                int am[8] = {a0.x, a0.y, a0.z, a0.w, a1.x, a1.y, a1.z, a1.w};
                #pragma unroll
                for (int e = 0; e < 8; e++) {
                    float2 t = __ldg(&g_tab[j0 + jl0 + e]);
                    float pv = Ai * t.x;
                    float v = (pv > 1.f) ? pv : Ci * t.y;
                    p[e] = (am[e] > 0) ? v : 0.f;
                }
            } else {
                #pragma unroll
                for (int e = 0; e < 8; e++) {
                    int j = j0 + jl0 + e;
                    int m = (j < N_KC) ? arow[j] : 0;
                    float2 t = __ldg(&g_tab[(j < N_KC) ? j : 0]);
                    float pv = Ai * t.x;
                    float v = (pv > 1.f) ? pv : Ci * t.y;
                    p[e] = (m > 0) ? v : 0.f;
                }
            }
            #pragma unroll
            for (int e = 0; e < 8; e++) srow += p[e];
            __half2 q0 = __floats2half2_rn(p[0], p[1]);
            __half2 q1 = __floats2half2_rn(p[2], p[3]);
            __half2 q2 = __floats2half2_rn(p[4], p[5]);
            __half2 q3 = __floats2half2_rn(p[6], p[7]);
            uint4 w = make_uint4(*(uint32_t*)&q0, *(uint32_t*)&q1,
                                 *(uint32_t*)&q2, *(uint32_t*)&q3);
            *(uint4*)(smem + AOF_A + buf * AOF_ASZ + r * RSTRIDE + jl0 * 2) = w;
        }

        CP_WAIT0();
        __syncthreads();

        if (c + 1 < c1)
            cp_b_chunk(sb + AOF_B + (buf ^ 1) * AOF_BSZ, c + 1, tid);

        uint32_t bBase = sb + AOF_B + buf * AOF_BSZ;
        #pragma unroll
        for (int ks = 0; ks < 2; ks++) {
            uint32_t af[2][4], bfrag[8][2];
            int arowi = lane & 15;
            int akoff = (ks * 16 + ((lane >> 4) & 1) * 8) * 2;
            #pragma unroll
            for (int mt = 0; mt < 2; mt++) {
                uint32_t ad = aBase + (wm * 32 + mt * 16 + arowi) * RSTRIDE + akoff;
                LDSM_X4(af[mt][0], af[mt][1], af[mt][2], af[mt][3], ad);
            }
            int bnrow = (lane & 7) + ((lane >> 4) << 3);
            int bkoff = (ks * 16 + ((lane >> 3) & 1) * 8) * 2;
            #pragma unroll
            for (int nq = 0; nq < 4; nq++) {
                uint32_t bd = bBase + (wn * 64 + nq * 16 + bnrow) * RSTRIDE + bkoff;
                LDSM_X4(bfrag[2 * nq][0], bfrag[2 * nq][1],
                        bfrag[2 * nq + 1][0], bfrag[2 * nq + 1][1], bd);
            }
            #pragma unroll
            for (int mt = 0; mt < 2; mt++)
                #pragma unroll
                for (int nb = 0; nb < 8; nb++)
                    mma_fp16(acc[mt][nb], af[mt], bfrag[nb]);
        }
    }

    __syncthreads();
    ((float*)(smem + AOF_RS))[tid] = srow;
    __syncthreads();
    if (tid < MT) {
        const float* r4 = (const float*)(smem + AOF_RS) + tid * 4;
        ((float*)(smem + AOF_RSF))[tid] = (r4[0] + r4[1]) + (r4[2] + r4[3]);
    }
    __syncthreads();
    const float* rsF = (const float*)(smem + AOF_RSF);

    #pragma unroll
    for (int mt = 0; mt < 2; mt++) {
        #pragma unroll
        for (int nb = 0; nb < 8; nb++) {
            int row0 = wm * 32 + mt * 16 + (lane >> 2);
            int col  = wn * 64 + nb * 8 + (lane & 3) * 2;
            #pragma unroll
            for (int h = 0; h < 2; h++) {
                int rr = row0 + h * 8;
                int gi = i0 + rr;
                if (gi >= N_E) continue;
                *(float2*)&g_pacc[half][(size_t)gi * OUT_F + col] =
                    make_float2(acc[mt][nb][2 * h], acc[mt][nb][2 * h + 1]);
            }
        }
    }
    if (tid < MT) g_psr[half][tile * MT + tid] = rsF[tid];
    __threadfence();
    __syncthreads();

    __shared__ int sLast;
    if (tid == 0) sLast = (atomicAdd(&g_cnt[tile], 1) == 1);
    __syncthreads();
    if (!sLast) return;

    int other = half ^ 1;
    if (tid < MT)
        ((float*)(smem + AOF_RS))[tid] = rsF[tid] + g_psr[other][tile * MT + tid];
    __syncthreads();
    const float* rsC = (const float*)(smem + AOF_RS);

    #pragma unroll
    for (int mt = 0; mt < 2; mt++) {
        #pragma unroll
        for (int nb = 0; nb < 8; nb++) {
            int row0 = wm * 32 + mt * 16 + (lane >> 2);
            int col  = wn * 64 + nb * 8 + (lane & 3) * 2;
            #pragma unroll
            for (int h = 0; h < 2; h++) {
                int rr = row0 + h * 8;
                int gi = i0 + rr;
                if (gi >= N_E) continue;
                float2 po = *(const float2*)&g_pacc[other][(size_t)gi * OUT_F + col];
                float v0 = acc[mt][nb][2 * h]     + po.x;
                float v1 = acc[mt][nb][2 * h + 1] + po.y;
                float rs = rsC[rr];
                float nk0, nk1;
                if (rs > 0.f) {
                    float ri = 1.f / rs;
                    nk0 = v0 * ri;
                    nk1 = v1 * ri;
                } else {
                    nk0 = g_colmean[col];
                    nk1 = g_colmean[col + 1];
                }
                __half2 t = __floats2half2_rn(nk0, nk1);
                *(uint32_t*)(g_feath + (size_t)gi * OUT_F + col) = *(uint32_t*)&t;
            }
        }
    }
}

// ---------------- fused kernel: attention split-K + exEh fp16 GEMM tail ----------------
__global__ __launch_bounds__(256, 2) void attn_fused_kernel(const int* __restrict__ adj)
{
    extern __shared__ char smem[];
    if (blockIdx.x < NATTN2) {
        attn_body(smem, (int)(blockIdx.x >> 1), (int)(blockIdx.x & 1), adj);
    } else {
        int g = blockIdx.x - NATTN2;
        hgemm_body(smem, (const bf16*)g_exh, nullptr, (const bf16*)g_ETh, nullptr,
                   (float*)g_exEhh, N_E, OUT_F, IN_F, 3, g & 1, g >> 1, 1);
    }
}

// ---------------- launch ----------------
extern "C" void kernel_launch(void* const* d_in, const int* in_sizes, int n_in,
                              void* d_out, int out_size)
{
    const float* ex   = (const float*)d_in[0];
    const float* kc   = (const float*)d_in[1];
    const int*   adj  = (const int*)d_in[2];
    const float* W1   = (const float*)d_in[3];
    const float* E    = (const float*)d_in[4];
    const float* a    = (const float*)d_in[5];
    const float* rd_w = (const float*)d_in[6];
    const float* rd_b = (const float*)d_in[7];
    float* out = (float*)d_out;

    cudaFuncSetAttribute(attn_fused_kernel,
                         cudaFuncAttributeMaxDynamicSharedMemorySize, SMEM_ATTN);
    cudaFuncSetAttribute(prep2_kernel,
                         cudaFuncAttributeMaxDynamicSharedMemorySize, 40960);

    // 0. v1/v2 + flag reset + tab padding
    k0_kernel<<<1, 256>>>(W1, a);

    // 1. conversions + fused e1/e2 rowdots + exp tables + kc colsum partials
    mega_kernel<<<MB_TOT, 256>>>(ex, kc, rd_w, W1, E);

    // 2. kcWh gemm (-> g_kcWhT fp16) + colmean
    prep2_kernel<<<P2_TOT, 256, 40960>>>(W1);

    // 3. fused: attention split-K (314) + exEh fp16 GEMM (158)
    attn_fused_kernel<<<NATTN2 + NGEX, 256, SMEM_ATTN>>>(adj);

    // 4. out = elu([nk | nk*exEh] @ rd_w^T + rd_b), 64x64 tiles, fp16
    fgemm64_kernel<<<dim3(4, (N_E + 63) / 64), 256>>>(rd_b, out);
}